// round 17
// baseline (speedup 1.0000x reference)
#include <cuda_runtime.h>
#include <math.h>
#include <stdint.h>

// Problem constants (fixed by setup_inputs)
#define S0   2048
#define S1   256
#define ST   2304          // S0 + S1
#define NH   24            // heads
#define HD   64            // dim_head
#define DIM  1536          // model dim == NH*HD
#define NQKV 4608          // 3*NH*HD

// ---------------- scratch (static device globals; no allocation) -----------
__device__ float g_qkv[ST * NQKV];        // (s, 3*H*D) packed both modalities
__device__ float g_attn[ST * DIM];        // (s, h*d) attention output

// pre-split Q/K/V: interleaved (hi, lo) tf32 pairs, element (h,s,d) at [(h*ST+s)*HD+d]
__device__ __align__(16) uint2 g_Qs[NH * ST * HD];
__device__ __align__(16) uint2 g_Ks[NH * ST * HD];
__device__ __align__(16) uint2 g_Vs[NH * ST * HD];

// pre-split weights: interleaved (hi, lo) tf32 pairs, element (k,n) at [k*N+n]
__device__ __align__(16) uint2 g_wqkv0s[DIM * NQKV];
__device__ __align__(16) uint2 g_wqkv1s[DIM * NQKV];
__device__ __align__(16) uint2 g_wout0s[DIM * DIM];
__device__ __align__(16) uint2 g_wout1s[DIM * DIM];

// ---------------------------------------------------------------------------
// tf32 helpers (shared fragment conventions for all MMA kernels)
// ---------------------------------------------------------------------------
__device__ __forceinline__ uint32_t f32_to_tf32(float x) {
    uint32_t u;
    asm("cvt.rna.tf32.f32 %0, %1;" : "=r"(u) : "f"(x));
    return u;
}

// split x = hi + lo with hi = tf32(x); the subtraction is exact.
__device__ __forceinline__ void tf32_split(float x, uint32_t& hi, uint32_t& lo) {
    hi = f32_to_tf32(x);
    lo = f32_to_tf32(x - __uint_as_float(hi));
}

__device__ __forceinline__ void mma_tf32(float c[4], const uint32_t a[4],
                                         const uint32_t b[2]) {
    asm volatile(
        "mma.sync.aligned.m16n8k8.row.col.f32.tf32.tf32.f32 "
        "{%0,%1,%2,%3}, {%4,%5,%6,%7}, {%8,%9}, {%0,%1,%2,%3};"
        : "+f"(c[0]), "+f"(c[1]), "+f"(c[2]), "+f"(c[3])
        : "r"(a[0]), "r"(a[1]), "r"(a[2]), "r"(a[3]), "r"(b[0]), "r"(b[1]));
}

__device__ __forceinline__ void cp_async16(uint32_t smem_addr, const void* gptr) {
    asm volatile("cp.async.cg.shared.global [%0], [%1], 16;"
                 :: "r"(smem_addr), "l"(gptr));
}
__device__ __forceinline__ void cp_async_commit() {
    asm volatile("cp.async.commit_group;");
}
__device__ __forceinline__ void cp_async_wait0() {
    asm volatile("cp.async.wait_group 0;");
}

// ---------------------------------------------------------------------------
// Weight pre-split: out[i] = (tf32(x), tf32(x - tf32(x))) interleaved.
// ---------------------------------------------------------------------------
__global__ __launch_bounds__(256) void split_kernel(
    const float* __restrict__ in, uint2* __restrict__ out, int n)
{
    int i = (blockIdx.x * 256 + threadIdx.x) * 4;
    if (i >= n) return;
    float4 v = *(const float4*)&in[i];
    uint4 o0, o1;
    tf32_split(v.x, o0.x, o0.y);
    tf32_split(v.y, o0.z, o0.w);
    tf32_split(v.z, o1.x, o1.y);
    tf32_split(v.w, o1.z, o1.w);
    *(uint4*)&out[i]     = o0;
    *(uint4*)&out[i + 2] = o1;
}

// ---------------------------------------------------------------------------
// 3xTF32 tensor-core GEMM, dual-segment (two modalities in one launch):
//   rows [0, M0)      : C0 = A0 * B0s
//   rows [M0, ...)    : C1 = A1 * B1s
// A row-major fp32 (split on staging); B pre-split interleaved (hi,lo).
// Block tile 128x128, BK=16, 256 threads = 8 warps (4m x 2n), warp = m32 x n64.
// Double-buffered SMEM, interleaved hi/lo, pitch 264 u32 (8 mod 32) ->
// conflict-free LDS.64 fragment loads. B staged via cp.async (pure copy).
// ---------------------------------------------------------------------------
#define GPA 264                              // SMEM pitch (u32 units)
#define GEMM_TILE_U32 (16 * GPA)             // [16][264] tile
#define GEMM_BUF_U32  (2 * GEMM_TILE_U32)    // A + B per buffer
#define GEMM_SMEM_BYTES (2 * GEMM_BUF_U32 * 4)   // 67,584 B

extern __shared__ uint32_t gsm[];

__global__ __launch_bounds__(256, 2) void gemm_tf32x3_dual_kernel(
    const float* __restrict__ A0, const uint2* __restrict__ B0, float* __restrict__ C0,
    const float* __restrict__ A1, const uint2* __restrict__ B1, float* __restrict__ C1,
    int M0, int N, int K)
{
    const int tid  = threadIdx.x;
    const int warp = tid >> 5;
    const int lane = tid & 31;
    const int wm   = warp >> 1;       // 0..3  (m32 slab)
    const int wn   = warp & 1;        // 0..1  (n64 slab)

    // segment select
    const int my = blockIdx.y * 128;
    const float* A; const uint2* B; float* C;
    int m0;
    if (my < M0) { A = A0; B = B0; C = C0; m0 = my; }
    else         { A = A1; B = B1; C = C1; m0 = my - M0; }
    const int n0 = blockIdx.x * 128;

    const int ra = lane >> 2;         // 0..7
    const int ca = lane & 3;          // 0..3

    // A staging map (2 passes): row arow0 + i*64, k cols acol..acol+3
    const int arow0 = tid >> 2;               // 0..63
    const int acol  = (tid & 3) << 2;         // 0,4,8,12
    const float* Aptr = A + (size_t)(m0 + arow0) * K + acol;

    // B staging map (4 cp.async of 16B per tile)
    const uint32_t* Bu = (const uint32_t*)B;
    const int bkrow = tid >> 6;               // base k row 0..3 (+4 per i)
    const int bc    = (tid & 63) << 2;        // u32 col 0..252

    float acc[2][8][4];
    #pragma unroll
    for (int i = 0; i < 2; i++)
        #pragma unroll
        for (int j = 0; j < 8; j++)
            #pragma unroll
            for (int r = 0; r < 4; r++)
                acc[i][j][r] = 0.0f;

    float4 avr[2];

    // ---- prologue: stage tile 0 ----
    {
        uint32_t* As = gsm;
        uint32_t* Bs = gsm + GEMM_TILE_U32;
        #pragma unroll
        for (int i = 0; i < 4; i++) {
            int krow = bkrow + i * 4;
            uint32_t dst = (uint32_t)__cvta_generic_to_shared(&Bs[krow * GPA + bc]);
            cp_async16(dst, Bu + 2 * ((size_t)krow * N + n0) + bc);
        }
        cp_async_commit();
        #pragma unroll
        for (int i = 0; i < 2; i++)
            avr[i] = *(const float4*)(Aptr + (size_t)i * 64 * K);
        #pragma unroll
        for (int i = 0; i < 2; i++) {
            const int arow = arow0 + i * 64;
            float af[4] = {avr[i].x, avr[i].y, avr[i].z, avr[i].w};
            #pragma unroll
            for (int j = 0; j < 4; j++) {
                uint32_t hi, lo;
                tf32_split(af[j], hi, lo);
                *(uint2*)&As[(acol + j) * GPA + 2 * arow] = make_uint2(hi, lo);
            }
        }
        cp_async_wait0();
        __syncthreads();
    }

    const int ntiles = K >> 4;
    for (int kt = 0; kt < ntiles; kt++) {
        const int cur = kt & 1;
        const int nxt = cur ^ 1;
        uint32_t* Asc = gsm + cur * GEMM_BUF_U32;
        uint32_t* Bsc = Asc + GEMM_TILE_U32;

        // ---- issue next-tile staging (B async, A prefetch to regs) ----
        if (kt + 1 < ntiles) {
            uint32_t* Bsn = gsm + nxt * GEMM_BUF_U32 + GEMM_TILE_U32;
            #pragma unroll
            for (int i = 0; i < 4; i++) {
                int krow = bkrow + i * 4;
                uint32_t dst = (uint32_t)__cvta_generic_to_shared(&Bsn[krow * GPA + bc]);
                cp_async16(dst, Bu + 2 * ((size_t)((kt + 1) * 16 + krow) * N + n0) + bc);
            }
            cp_async_commit();
            #pragma unroll
            for (int i = 0; i < 2; i++)
                avr[i] = *(const float4*)(Aptr + (size_t)i * 64 * K + (kt + 1) * 16);
        }

        // ---- compute on current buffer: 2 k-steps of 8 ----
        #pragma unroll
        for (int ks = 0; ks < 2; ks++) {
            const int k4 = ks * 8;
            uint32_t ah[2][4], al[2][4], bh[8][2], bl[8][2];

            #pragma unroll
            for (int mt = 0; mt < 2; mt++) {
                int mrow = wm * 32 + mt * 16;
                uint2 t0 = *(const uint2*)&Asc[(k4 + ca) * GPA + 2 * (mrow + ra)];
                uint2 t1 = *(const uint2*)&Asc[(k4 + ca) * GPA + 2 * (mrow + ra + 8)];
                uint2 t2 = *(const uint2*)&Asc[(k4 + ca + 4) * GPA + 2 * (mrow + ra)];
                uint2 t3 = *(const uint2*)&Asc[(k4 + ca + 4) * GPA + 2 * (mrow + ra + 8)];
                ah[mt][0] = t0.x; al[mt][0] = t0.y;
                ah[mt][1] = t1.x; al[mt][1] = t1.y;
                ah[mt][2] = t2.x; al[mt][2] = t2.y;
                ah[mt][3] = t3.x; al[mt][3] = t3.y;
            }
            #pragma unroll
            for (int nt = 0; nt < 8; nt++) {
                int ncol = wn * 64 + nt * 8 + ra;
                uint2 u0 = *(const uint2*)&Bsc[(k4 + ca) * GPA + 2 * ncol];
                uint2 u1 = *(const uint2*)&Bsc[(k4 + ca + 4) * GPA + 2 * ncol];
                bh[nt][0] = u0.x; bl[nt][0] = u0.y;
                bh[nt][1] = u1.x; bl[nt][1] = u1.y;
            }

            #pragma unroll
            for (int mt = 0; mt < 2; mt++)
                #pragma unroll
                for (int nt = 0; nt < 8; nt++) {
                    mma_tf32(acc[mt][nt], al[mt], bh[nt]);
                    mma_tf32(acc[mt][nt], ah[mt], bl[nt]);
                    mma_tf32(acc[mt][nt], ah[mt], bh[nt]);
                }
        }

        // ---- finish staging next buffer ----
        if (kt + 1 < ntiles) {
            uint32_t* Asn = gsm + nxt * GEMM_BUF_U32;
            #pragma unroll
            for (int i = 0; i < 2; i++) {
                const int arow = arow0 + i * 64;
                float af[4] = {avr[i].x, avr[i].y, avr[i].z, avr[i].w};
                #pragma unroll
                for (int j = 0; j < 4; j++) {
                    uint32_t hi, lo;
                    tf32_split(af[j], hi, lo);
                    *(uint2*)&Asn[(acol + j) * GPA + 2 * arow] = make_uint2(hi, lo);
                }
            }
            cp_async_wait0();
            __syncthreads();
        }
    }

    // ---- epilogue ----
    #pragma unroll
    for (int mt = 0; mt < 2; mt++) {
        int gr = m0 + wm * 32 + mt * 16 + ra;
        #pragma unroll
        for (int nt = 0; nt < 8; nt++) {
            int gc = n0 + wn * 64 + nt * 8 + ca * 2;
            *(float2*)&C[(size_t)gr * N + gc] =
                make_float2(acc[mt][nt][0], acc[mt][nt][1]);
            *(float2*)&C[(size_t)(gr + 8) * N + gc] =
                make_float2(acc[mt][nt][2], acc[mt][nt][3]);
        }
    }
}

// ---------------------------------------------------------------------------
// QKV epilogue: per token s, per head: RMSNorm(q,k) + RoPE(q,k), copy v.
// Writes PRE-SPLIT interleaved (hi,lo) tf32 pairs; Q carries the 1/8 softmax
// scale (exact power-of-two multiply). Attention then stages via pure cp.async.
// ---------------------------------------------------------------------------
__global__ __launch_bounds__(256) void qkv_epilogue_kernel(
    const float* __restrict__ gq0, const float* __restrict__ gk0,
    const float* __restrict__ gq1, const float* __restrict__ gk1)
{
    const int s = blockIdx.x;
    const int modality = (s < S0) ? 0 : 1;
    const int s_local  = modality ? (s - S0) : s;
    const float* gq = modality ? gq1 : gq0;
    const float* gk = modality ? gk1 : gk0;

    const int warp = threadIdx.x >> 5;
    const int lane = threadIdx.x & 31;

    float inv = __powf(10000.0f, -(float)lane / 32.0f);
    float ang = (float)s_local * inv;
    float c, sn;
    sincosf(ang, &sn, &c);

    const float* row = g_qkv + (size_t)s * NQKV;

    for (int h = warp; h < NH; h += 8) {
        const size_t base = ((size_t)h * ST + s) * HD;
        {
            float x0 = row[0 * DIM + h * HD + lane];
            float x1 = row[0 * DIM + h * HD + lane + 32];
            float ss = x0 * x0 + x1 * x1;
            #pragma unroll
            for (int off = 16; off > 0; off >>= 1)
                ss += __shfl_xor_sync(0xffffffffu, ss, off);
            float r = rsqrtf(ss * (1.0f / 64.0f) + 1e-6f);
            float q0 = x0 * r * gq[lane];
            float q1 = x1 * r * gq[lane + 32];
            uint32_t hi, lo;
            tf32_split((q0 * c - q1 * sn) * 0.125f, hi, lo);
            g_Qs[base + lane]      = make_uint2(hi, lo);
            tf32_split((q1 * c + q0 * sn) * 0.125f, hi, lo);
            g_Qs[base + lane + 32] = make_uint2(hi, lo);
        }
        {
            float x0 = row[1 * DIM + h * HD + lane];
            float x1 = row[1 * DIM + h * HD + lane + 32];
            float ss = x0 * x0 + x1 * x1;
            #pragma unroll
            for (int off = 16; off > 0; off >>= 1)
                ss += __shfl_xor_sync(0xffffffffu, ss, off);
            float r = rsqrtf(ss * (1.0f / 64.0f) + 1e-6f);
            float k0 = x0 * r * gk[lane];
            float k1 = x1 * r * gk[lane + 32];
            uint32_t hi, lo;
            tf32_split(k0 * c - k1 * sn, hi, lo);
            g_Ks[base + lane]      = make_uint2(hi, lo);
            tf32_split(k1 * c + k0 * sn, hi, lo);
            g_Ks[base + lane + 32] = make_uint2(hi, lo);
        }
        {
            uint32_t hi, lo;
            tf32_split(row[2 * DIM + h * HD + lane], hi, lo);
            g_Vs[base + lane]      = make_uint2(hi, lo);
            tf32_split(row[2 * DIM + h * HD + lane + 32], hi, lo);
            g_Vs[base + lane + 32] = make_uint2(hi, lo);
        }
    }
}

// ---------------------------------------------------------------------------
// Tensor-core attention: softmax(Q K^T / 8) V per head, 3xTF32 everywhere.
// Block = 128 queries x one head, 256 threads = 8 warps; warp owns m16 rows.
// Q/K/V are PRE-SPLIT in global (interleaved hi/lo) -> staging is pure
// cp.async; K/V double-buffered to overlap loads with MMA compute.
// SMEM pitch 136 u32 (8 mod 32) -> conflict-free LDS.64 fragment loads.
// No online max (|score| <= 8 by RMS-norm bound).
// P converted C-layout -> A-layout by warp shuffles (no SMEM round-trip).
// ---------------------------------------------------------------------------
#define AQ_BQ   128
#define AQ_BK   64
#define AQ_P    136                      // pitch in u32 (2*HD + 8 pad)
#define AQ_NT   (ST / AQ_BK)             // 36 key tiles
// layout: Q[128] | K0[64] | K1[64] | V0[64] | V1[64]  (rows of AQ_P u32)
#define ATTN_SMEM_BYTES ((AQ_BQ + 4 * AQ_BK) * AQ_P * 4)   // 208,896

extern __shared__ uint32_t attn_sm[];

__global__ __launch_bounds__(256) void attn_mma_kernel()
{
    uint32_t* Qs = attn_sm;                                     // [128][AQ_P]
    uint32_t* Kb[2] = { attn_sm + AQ_BQ * AQ_P,
                        attn_sm + (AQ_BQ + AQ_BK) * AQ_P };
    uint32_t* Vb[2] = { attn_sm + (AQ_BQ + 2 * AQ_BK) * AQ_P,
                        attn_sm + (AQ_BQ + 3 * AQ_BK) * AQ_P };

    const int tid  = threadIdx.x;
    const int warp = tid >> 5;           // 0..7 -> query rows [warp*16, +16)
    const int lane = tid & 31;
    const int ra   = lane >> 2;          // 0..7
    const int ca   = lane & 3;           // 0..3
    const int h    = blockIdx.y;
    const int qb   = blockIdx.x * AQ_BQ;

    const uint32_t* Qg = (const uint32_t*)g_Qs + ((size_t)h * ST + qb) * 128;
    const uint32_t* KgBase = (const uint32_t*)g_Ks + (size_t)h * ST * 128;
    const uint32_t* VgBase = (const uint32_t*)g_Vs + (size_t)h * ST * 128;

    // ---- prologue: stage Q slab + K/V tile 0, all via cp.async ----
    #pragma unroll
    for (int i = 0; i < 16; i++) {
        int idx = tid + i * 256;         // 0..4095 16B-chunk ids
        int q = idx >> 5;
        int c = (idx & 31) << 2;         // u32 col 0..124
        uint32_t dst = (uint32_t)__cvta_generic_to_shared(&Qs[q * AQ_P + c]);
        cp_async16(dst, Qg + (size_t)q * 128 + c);
    }
    #pragma unroll
    for (int i = 0; i < 8; i++) {
        int idx = tid + i * 256;         // 0..2047
        int r = idx >> 5;
        int c = (idx & 31) << 2;
        uint32_t dk = (uint32_t)__cvta_generic_to_shared(&Kb[0][r * AQ_P + c]);
        cp_async16(dk, KgBase + (size_t)r * 128 + c);
        uint32_t dv = (uint32_t)__cvta_generic_to_shared(&Vb[0][r * AQ_P + c]);
        cp_async16(dv, VgBase + (size_t)r * 128 + c);
    }
    cp_async_commit();

    float oacc[8][4];
    #pragma unroll
    for (int nt = 0; nt < 8; nt++)
        #pragma unroll
        for (int r = 0; r < 4; r++) oacc[nt][r] = 0.0f;
    float l0 = 0.0f, l1 = 0.0f;

    const int q0 = warp * 16;
    const int src1 = (lane & ~3) | (ca >> 1);   // shfl source A
    const int src2 = src1 + 2;                  // shfl source B
    const bool odd = ca & 1;

    cp_async_wait0();
    __syncthreads();

    for (int kt = 0; kt < AQ_NT; kt++) {
        const int cur = kt & 1;
        const int nxt = cur ^ 1;
        uint32_t* Ks = Kb[cur];
        uint32_t* Vs = Vb[cur];

        // ---- issue next K/V tile into the other buffer ----
        if (kt + 1 < AQ_NT) {
            const uint32_t* Kg = KgBase + (size_t)(kt + 1) * AQ_BK * 128;
            const uint32_t* Vg = VgBase + (size_t)(kt + 1) * AQ_BK * 128;
            #pragma unroll
            for (int i = 0; i < 8; i++) {
                int idx = tid + i * 256;
                int r = idx >> 5;
                int c = (idx & 31) << 2;
                uint32_t dk = (uint32_t)__cvta_generic_to_shared(&Kb[nxt][r * AQ_P + c]);
                cp_async16(dk, Kg + (size_t)r * 128 + c);
                uint32_t dv = (uint32_t)__cvta_generic_to_shared(&Vb[nxt][r * AQ_P + c]);
                cp_async16(dv, Vg + (size_t)r * 128 + c);
            }
            cp_async_commit();
        }

        // ---- scores: S[16 q][64 key] = Q . K^T  (reduce over d) ----
        float p[8][4];
        #pragma unroll
        for (int nt = 0; nt < 8; nt++)
            #pragma unroll
            for (int r = 0; r < 4; r++) p[nt][r] = 0.0f;

        #pragma unroll
        for (int kk = 0; kk < 8; kk++) {
            uint32_t ah[4], al[4];
            uint2 t0 = *(const uint2*)&Qs[(q0 + ra)     * AQ_P + 2 * (kk * 8 + ca)];
            uint2 t1 = *(const uint2*)&Qs[(q0 + ra + 8) * AQ_P + 2 * (kk * 8 + ca)];
            uint2 t2 = *(const uint2*)&Qs[(q0 + ra)     * AQ_P + 2 * (kk * 8 + ca + 4)];
            uint2 t3 = *(const uint2*)&Qs[(q0 + ra + 8) * AQ_P + 2 * (kk * 8 + ca + 4)];
            ah[0] = t0.x; al[0] = t0.y;
            ah[1] = t1.x; al[1] = t1.y;
            ah[2] = t2.x; al[2] = t2.y;
            ah[3] = t3.x; al[3] = t3.y;
            #pragma unroll
            for (int nt = 0; nt < 8; nt++) {
                uint32_t bh[2], bl[2];
                uint2 u0 = *(const uint2*)&Ks[(nt * 8 + ra) * AQ_P + 2 * (kk * 8 + ca)];
                uint2 u1 = *(const uint2*)&Ks[(nt * 8 + ra) * AQ_P + 2 * (kk * 8 + ca + 4)];
                bh[0] = u0.x; bl[0] = u0.y;
                bh[1] = u1.x; bl[1] = u1.y;
                mma_tf32(p[nt], al, bh);
                mma_tf32(p[nt], ah, bl);
                mma_tf32(p[nt], ah, bh);
            }
        }

        // ---- softmax numerators + row-sum accumulation ----
        float rs0 = 0.0f, rs1 = 0.0f;
        #pragma unroll
        for (int nt = 0; nt < 8; nt++) {
            p[nt][0] = __expf(p[nt][0]);
            p[nt][1] = __expf(p[nt][1]);
            p[nt][2] = __expf(p[nt][2]);
            p[nt][3] = __expf(p[nt][3]);
            rs0 += p[nt][0] + p[nt][1];
            rs1 += p[nt][2] + p[nt][3];
        }
        rs0 += __shfl_xor_sync(0xffffffffu, rs0, 1);
        rs0 += __shfl_xor_sync(0xffffffffu, rs0, 2);
        rs1 += __shfl_xor_sync(0xffffffffu, rs1, 1);
        rs1 += __shfl_xor_sync(0xffffffffu, rs1, 2);
        l0 += rs0;
        l1 += rs1;

        // ---- O += P . V  (reduce over keys); P via shuffle to A-layout ----
        #pragma unroll
        for (int kk = 0; kk < 8; kk++) {
            float v0a = __shfl_sync(0xffffffffu, p[kk][0], src1);
            float v1a = __shfl_sync(0xffffffffu, p[kk][1], src1);
            float v2a = __shfl_sync(0xffffffffu, p[kk][2], src1);
            float v3a = __shfl_sync(0xffffffffu, p[kk][3], src1);
            float v0b = __shfl_sync(0xffffffffu, p[kk][0], src2);
            float v1b = __shfl_sync(0xffffffffu, p[kk][1], src2);
            float v2b = __shfl_sync(0xffffffffu, p[kk][2], src2);
            float v3b = __shfl_sync(0xffffffffu, p[kk][3], src2);
            uint32_t ah[4], al[4];
            tf32_split(odd ? v1a : v0a, ah[0], al[0]);   // (row ra,   col ca)
            tf32_split(odd ? v3a : v2a, ah[1], al[1]);   // (row ra+8, col ca)
            tf32_split(odd ? v1b : v0b, ah[2], al[2]);   // (row ra,   col ca+4)
            tf32_split(odd ? v3b : v2b, ah[3], al[3]);   // (row ra+8, col ca+4)
            #pragma unroll
            for (int nt = 0; nt < 8; nt++) {
                uint32_t bh[2], bl[2];
                uint2 u0 = *(const uint2*)&Vs[(kk * 8 + ca)     * AQ_P + 2 * (nt * 8 + ra)];
                uint2 u1 = *(const uint2*)&Vs[(kk * 8 + ca + 4) * AQ_P + 2 * (nt * 8 + ra)];
                bh[0] = u0.x; bl[0] = u0.y;
                bh[1] = u1.x; bl[1] = u1.y;
                mma_tf32(oacc[nt], al, bh);
                mma_tf32(oacc[nt], ah, bl);
                mma_tf32(oacc[nt], ah, bh);
            }
        }

        // ---- retire this tile; make next buffer visible ----
        if (kt + 1 < AQ_NT) {
            cp_async_wait0();
            __syncthreads();
        }
    }

    // ---- epilogue: divide by row sums, write (s, h*d) layout ----
    const float il0 = 1.0f / l0;
    const float il1 = 1.0f / l1;
    const int gq0r = qb + q0 + ra;
    #pragma unroll
    for (int nt = 0; nt < 8; nt++) {
        int gc = h * HD + nt * 8 + ca * 2;
        *(float2*)&g_attn[(size_t)gq0r * DIM + gc] =
            make_float2(oacc[nt][0] * il0, oacc[nt][1] * il0);
        *(float2*)&g_attn[(size_t)(gq0r + 8) * DIM + gc] =
            make_float2(oacc[nt][2] * il1, oacc[nt][3] * il1);
    }
}

// ---------------------------------------------------------------------------
extern "C" void kernel_launch(void* const* d_in, const int* in_sizes, int n_in,
                              void* d_out, int out_size)
{
    const float* x0     = (const float*)d_in[0];
    const float* x1     = (const float*)d_in[1];
    const float* w_qkv0 = (const float*)d_in[2];
    const float* w_qkv1 = (const float*)d_in[3];
    const float* w_out0 = (const float*)d_in[4];
    const float* w_out1 = (const float*)d_in[5];
    const float* gq0    = (const float*)d_in[6];
    const float* gk0    = (const float*)d_in[7];
    const float* gq1    = (const float*)d_in[8];
    const float* gk1    = (const float*)d_in[9];
    float* out = (float*)d_out;

    float *qkv, *attn;
    uint2 *wqkv0s, *wqkv1s, *wout0s, *wout1s;
    cudaGetSymbolAddress((void**)&qkv,    g_qkv);
    cudaGetSymbolAddress((void**)&attn,   g_attn);
    cudaGetSymbolAddress((void**)&wqkv0s, g_wqkv0s);
    cudaGetSymbolAddress((void**)&wqkv1s, g_wqkv1s);
    cudaGetSymbolAddress((void**)&wout0s, g_wout0s);
    cudaGetSymbolAddress((void**)&wout1s, g_wout1s);

    cudaFuncSetAttribute(gemm_tf32x3_dual_kernel,
                         cudaFuncAttributeMaxDynamicSharedMemorySize, GEMM_SMEM_BYTES);
    cudaFuncSetAttribute(attn_mma_kernel,
                         cudaFuncAttributeMaxDynamicSharedMemorySize, ATTN_SMEM_BYTES);

    // 0) pre-split weights into interleaved (hi, lo)
    const int nqkvw = DIM * NQKV, noutw = DIM * DIM;
    split_kernel<<<(nqkvw / 4 + 255) / 256, 256>>>(w_qkv0, wqkv0s, nqkvw);
    split_kernel<<<(nqkvw / 4 + 255) / 256, 256>>>(w_qkv1, wqkv1s, nqkvw);
    split_kernel<<<(noutw / 4 + 255) / 256, 256>>>(w_out0, wout0s, noutw);
    split_kernel<<<(noutw / 4 + 255) / 256, 256>>>(w_out1, wout1s, noutw);

    // 1) QKV projections, both modalities in one launch (grid.y spans S0+S1)
    gemm_tf32x3_dual_kernel<<<dim3(NQKV / 128, ST / 128), 256, GEMM_SMEM_BYTES>>>(
        x0, wqkv0s, qkv,
        x1, wqkv1s, qkv + (size_t)S0 * NQKV,
        S0, NQKV, DIM);

    // 2) rmsnorm + RoPE + pre-split scatter to (h,s,d)
    qkv_epilogue_kernel<<<ST, 256>>>(gq0, gk0, gq1, gk1);

    // 3) joint attention over packed sequence (tensor cores, cp.async staged)
    attn_mma_kernel<<<dim3(ST / AQ_BQ, NH), 256, ATTN_SMEM_BYTES>>>();

    // 4) output projections, both modalities in one launch
    gemm_tf32x3_dual_kernel<<<dim3(DIM / 128, ST / 128), 256, GEMM_SMEM_BYTES>>>(
        attn, wout0s, out,
        attn + (size_t)S0 * DIM, wout1s, out + (size_t)S0 * DIM,
        S0, DIM, DIM);
}